// round 14
// baseline (speedup 1.0000x reference)
#include <cuda_runtime.h>
#include <cuda_fp16.h>
#include <math.h>
#include <stdint.h>

// Problem constants
#define BB 2
#define NN 2048
#define DD 1024
#define HH 16
#define HDIM 64
#define MM (BB*NN)   // 4096

// q pre-scale: (1/sqrt(64)) * log2(e)  -> softmax computed with exp2
#define SCALE_LOG2 0.18033688011112042f

// ---------------------------------------------------------------------------
// Device scratch
// ---------------------------------------------------------------------------
__device__ __half g_qh [BB*HH*NN*HDIM];  // pre-scaled by SCALE_LOG2
__device__ __half g_kh [BB*HH*NN*HDIM];
__device__ __half g_vh [BB*HH*NN*HDIM];
__device__ __half g_ch [MM*DD];     // ctx fp16

// ---------------------------------------------------------------------------
// PTX helpers (compute_103-safe: no 'a' features)
// ---------------------------------------------------------------------------
__device__ __forceinline__ uint32_t smem_u32(const void* p) {
    uint32_t a;
    asm("{ .reg .u64 t; cvta.to.shared.u64 t, %1; cvt.u32.u64 %0, t; }"
        : "=r"(a) : "l"(p));
    return a;
}
__device__ __forceinline__ void cp16(uint32_t dst, const void* src) {
    asm volatile("cp.async.cg.shared.global [%0], [%1], 16;" :: "r"(dst), "l"(src));
}
#define CP_COMMIT() asm volatile("cp.async.commit_group;")
#define CP_WAIT(n)  asm volatile("cp.async.wait_group %0;" :: "n"(n))

#define LDSM4(r, addr) \
    asm volatile("ldmatrix.sync.aligned.m8n8.x4.shared.b16 {%0,%1,%2,%3}, [%4];" \
        : "=r"((r)[0]), "=r"((r)[1]), "=r"((r)[2]), "=r"((r)[3]) : "r"(addr))
#define LDSM4T(r, addr) \
    asm volatile("ldmatrix.sync.aligned.m8n8.x4.trans.shared.b16 {%0,%1,%2,%3}, [%4];" \
        : "=r"((r)[0]), "=r"((r)[1]), "=r"((r)[2]), "=r"((r)[3]) : "r"(addr))

__device__ __forceinline__ void mma16816(float* d, const uint32_t* a,
                                         uint32_t b0, uint32_t b1) {
    asm volatile("mma.sync.aligned.m16n8k16.row.col.f32.f16.f16.f32 "
                 "{%0,%1,%2,%3}, {%4,%5,%6,%7}, {%8,%9}, {%0,%1,%2,%3};"
                 : "+f"(d[0]), "+f"(d[1]), "+f"(d[2]), "+f"(d[3])
                 : "r"(a[0]), "r"(a[1]), "r"(a[2]), "r"(a[3]), "r"(b0), "r"(b1));
}
__device__ __forceinline__ uint32_t pack_h2(float lo, float hi) {
    uint32_t r;
    asm("cvt.rn.f16x2.f32 %0, %1, %2;" : "=r"(r) : "f"(hi), "f"(lo));
    return r;
}
__device__ __forceinline__ uint32_t h2exp2(uint32_t x) {
    uint32_t y;
    asm("ex2.approx.f16x2 %0, %1;" : "=r"(y) : "r"(x));
    return y;
}
__device__ __forceinline__ uint32_t hadd2u(uint32_t a, uint32_t b) {
    uint32_t r;
    asm("add.f16x2 %0, %1, %2;" : "=r"(r) : "r"(a), "r"(b));
    return r;
}
__device__ __forceinline__ float h2sum(uint32_t v) {
    __half2 h = *reinterpret_cast<__half2*>(&v);
    return __half2float(__low2half(h)) + __half2float(__high2half(h));
}

// load 8 fp32, convert to 8 fp16 packed in 4 u32
__device__ __forceinline__ void ldg_cvt16(const float* p, uint32_t* q) {
    float4 v0 = *reinterpret_cast<const float4*>(p);
    float4 v1 = *reinterpret_cast<const float4*>(p + 4);
    __half2 a = __floats2half2_rn(v0.x, v0.y);
    __half2 b = __floats2half2_rn(v0.z, v0.w);
    __half2 c = __floats2half2_rn(v1.x, v1.y);
    __half2 d = __floats2half2_rn(v1.z, v1.w);
    q[0] = *reinterpret_cast<uint32_t*>(&a);
    q[1] = *reinterpret_cast<uint32_t*>(&b);
    q[2] = *reinterpret_cast<uint32_t*>(&c);
    q[3] = *reinterpret_cast<uint32_t*>(&d);
}
__device__ __forceinline__ void sts16(uint32_t addr, const uint32_t* q) {
    asm volatile("st.shared.v4.b32 [%0], {%1,%2,%3,%4};"
                 :: "r"(addr), "r"(q[0]), "r"(q[1]), "r"(q[2]), "r"(q[3]) : "memory");
}

// ---------------------------------------------------------------------------
// HMMA fp16 GEMM with FUSED fp32->fp16 conversion in the loaders.
// C[128x128] tile, BK=64, 3-buffer pipeline (regs-staged LDG for fused paths,
// cp.async for the fp16 A of the out-projection).
// B = W in ORIGINAL fp32 [k][n] layout; fragments via ldmatrix.trans.
// mode 0/1/2 -> g_qh/g_kh/g_vh head-split fp16; mode 3 -> fp32 out + bias.
// smem: 3 x (A 16KB | B 16KB) = 96KB dynamic.
// ---------------------------------------------------------------------------
#define GEMM_SMEM (3 * 32768)

template<bool CVTA>
__global__ void __launch_bounds__(256, 2)
gemm_hmma_kernel(const float* __restrict__ A32,
                 const __half* __restrict__ A16,
                 const float* __restrict__ W0, const float* __restrict__ W1,
                 const float* __restrict__ W2, const float* __restrict__ W3,
                 const float* __restrict__ bias,
                 float* __restrict__ outp,
                 int mode_base)
{
    extern __shared__ __align__(16) char gsm[];
    const uint32_t uS = smem_u32(gsm);

    const int tid  = threadIdx.x;
    const int wid  = tid >> 5;
    const int lane = tid & 31;
    const int mode = mode_base + blockIdx.z;
    const int m0 = blockIdx.y * 128;
    const int n0 = blockIdx.x * 128;

    const float* __restrict__ Wp =
        (mode == 0) ? W0 : (mode == 1) ? W1 : (mode == 2) ? W2 : W3;
    const float* __restrict__ Bp = Wp + n0;
    const float*  __restrict__ A32p = A32 + (size_t)m0 * DD;
    const __half* __restrict__ A16p = A16 + (size_t)m0 * DD;

    const int wm = (wid & 3) * 32;
    const int wn = (wid >> 2) * 64;

    float acc[2][8][4];
    #pragma unroll
    for (int i = 0; i < 2; i++)
        #pragma unroll
        for (int j = 0; j < 8; j++)
            #pragma unroll
            for (int q = 0; q < 4; q++) acc[i][j][q] = 0.f;

    // A smem addr for chunk (buf, ra, ca); B for (buf, rb, hb, cb)
    #define SA_OFF(buf, ra, ca) \
        ((uint32_t)((buf) * 32768 + (ra) * 128 + (((ca) ^ ((ra) & 7)) * 16)))
    #define SB_OFF(buf, rb, hb, cb) \
        ((uint32_t)((buf) * 32768 + 16384 + (hb) * 8192 + (rb) * 128 + (((cb) ^ ((rb) & 7)) * 16)))

    // prologue: stages 0 and 1
    #pragma unroll
    for (int st = 0; st < 2; st++) {
        if (CVTA) {
            #pragma unroll
            for (int i = 0; i < 4; i++) {
                int idx = i * 256 + tid;
                int ra = idx >> 3, ca = idx & 7;
                uint32_t t[4];
                ldg_cvt16(A32p + (size_t)ra * DD + st * 64 + ca * 8, t);
                sts16(uS + SA_OFF(st, ra, ca), t);
            }
        } else {
            #pragma unroll
            for (int i = 0; i < 4; i++) {
                int idx = i * 256 + tid;
                int ra = idx >> 3, ca = idx & 7;
                cp16(uS + SA_OFF(st, ra, ca), A16p + (size_t)ra * DD + st * 64 + ca * 8);
            }
            CP_COMMIT();
        }
        #pragma unroll
        for (int i = 0; i < 4; i++) {
            int idx = i * 256 + tid;
            int rb = idx >> 4, qb = idx & 15;
            int hb = qb >> 3, cb = qb & 7;
            uint32_t t[4];
            ldg_cvt16(Bp + (size_t)(st * 64 + rb) * DD + hb * 64 + cb * 8, t);
            sts16(uS + SB_OFF(st, rb, hb, cb), t);
        }
    }
    if (!CVTA) CP_WAIT(1);     // stage-0 A landed
    __syncthreads();

    const int NS = DD / 64;    // 16 stages
    for (int s = 0; s < NS; s++) {
        const int buf = s % 3;
        const bool pre = (s + 2 < NS);

        // issue loads for stage s+2 (A: regs or cp.async; B: regs)
        uint32_t rA[4][4], rB[4][4];
        if (pre) {
            const int k2 = (s + 2) * 64;
            if (CVTA) {
                #pragma unroll
                for (int i = 0; i < 4; i++) {
                    int idx = i * 256 + tid;
                    int ra = idx >> 3, ca = idx & 7;
                    ldg_cvt16(A32p + (size_t)ra * DD + k2 + ca * 8, rA[i]);
                }
            } else {
                #pragma unroll
                for (int i = 0; i < 4; i++) {
                    int idx = i * 256 + tid;
                    int ra = idx >> 3, ca = idx & 7;
                    cp16(uS + SA_OFF((s + 2) % 3, ra, ca),
                         A16p + (size_t)ra * DD + k2 + ca * 8);
                }
                CP_COMMIT();
            }
            #pragma unroll
            for (int i = 0; i < 4; i++) {
                int idx = i * 256 + tid;
                int rb = idx >> 4, qb = idx & 15;
                int hb = qb >> 3, cb = qb & 7;
                ldg_cvt16(Bp + (size_t)(k2 + rb) * DD + hb * 64 + cb * 8, rB[i]);
            }
        }

        // MMAs on buf
        const uint32_t bA  = uS + buf * 32768;
        const uint32_t bBh = bA + 16384 + (wid >> 2) * 8192;
        #pragma unroll
        for (int ks = 0; ks < 4; ks++) {
            uint32_t af[2][4];
            #pragma unroll
            for (int mt = 0; mt < 2; mt++) {
                int row = wm + mt * 16 + (lane & 15);
                int c = ks * 2 + (lane >> 4);
                LDSM4(af[mt], bA + row * 128 + ((c ^ (row & 7)) * 16));
            }
            #pragma unroll
            for (int np = 0; np < 4; np++) {
                uint32_t bf[4];
                int rowb = ks * 16 + ((lane >> 3) & 1) * 8 + (lane & 7);
                int ccb  = 2 * np + (lane >> 4);
                LDSM4T(bf, bBh + rowb * 128 + ((ccb ^ (rowb & 7)) * 16));
                #pragma unroll
                for (int mt = 0; mt < 2; mt++) {
                    mma16816(acc[mt][np * 2],     af[mt], bf[0], bf[1]);
                    mma16816(acc[mt][np * 2 + 1], af[mt], bf[2], bf[3]);
                }
            }
        }

        // store staged tiles for stage s+2
        if (pre) {
            const int b2 = (s + 2) % 3;
            if (CVTA) {
                #pragma unroll
                for (int i = 0; i < 4; i++) {
                    int idx = i * 256 + tid;
                    int ra = idx >> 3, ca = idx & 7;
                    sts16(uS + SA_OFF(b2, ra, ca), rA[i]);
                }
            }
            #pragma unroll
            for (int i = 0; i < 4; i++) {
                int idx = i * 256 + tid;
                int rb = idx >> 4, qb = idx & 15;
                int hb = qb >> 3, cb = qb & 7;
                sts16(uS + SB_OFF(b2, rb, hb, cb), rB[i]);
            }
        }

        if (!CVTA) {            // ensure A group (s+1) complete before barrier
            if (pre)            CP_WAIT(1);
            else if (s + 1 < NS) CP_WAIT(0);
        }
        __syncthreads();
    }
    #undef SA_OFF
    #undef SB_OFF

    if (mode < 3) {
        const float scale = (mode == 0) ? SCALE_LOG2 : 1.0f;
        __half* __restrict__ dst = (mode == 0) ? g_qh : (mode == 1) ? g_kh : g_vh;
        #pragma unroll
        for (int mt = 0; mt < 2; mt++) {
            int r = m0 + wm + mt * 16 + (lane >> 2);
            int bbv = r >> 11, seq = r & 2047;
            #pragma unroll
            for (int nt = 0; nt < 8; nt++) {
                int col = n0 + wn + nt * 8 + (lane & 3) * 2;
                int hh = col >> 6, hd = col & 63;
                size_t o = ((size_t)(bbv * HH + hh) * NN + seq) * HDIM + hd;
                *reinterpret_cast<__half2*>(dst + o) =
                    __floats2half2_rn(acc[mt][nt][0] * scale, acc[mt][nt][1] * scale);
                *reinterpret_cast<__half2*>(dst + o + 8 * HDIM) =
                    __floats2half2_rn(acc[mt][nt][2] * scale, acc[mt][nt][3] * scale);
            }
        }
    } else {
        #pragma unroll
        for (int mt = 0; mt < 2; mt++) {
            int r = m0 + wm + mt * 16 + (lane >> 2);
            #pragma unroll
            for (int nt = 0; nt < 8; nt++) {
                int col = n0 + wn + nt * 8 + (lane & 3) * 2;
                float b0 = bias[col], b1 = bias[col + 1];
                *reinterpret_cast<float2*>(outp + (size_t)r * DD + col) =
                    make_float2(acc[mt][nt][0] + b0, acc[mt][nt][1] + b1);
                *reinterpret_cast<float2*>(outp + (size_t)(r + 8) * DD + col) =
                    make_float2(acc[mt][nt][2] + b0, acc[mt][nt][3] + b1);
            }
        }
    }
}

// ---------------------------------------------------------------------------
// HMMA flash attention (round-13 structure) + ALiBi tile cutoff:
// tiles with slope2*dist > 34 have p < 2^-24 (zero in fp16 already) -> the
// key-tile loop stops at kt_lo = ceil((q0-63-34/slope2)/64). Exact vs r13.
// dynamic smem: Q 8KB | K 2x8KB | V 2x8KB = 40KB. grid (16,16,2), 128 thr.
// ---------------------------------------------------------------------------
#define ATTN_SMEM (40960)

__global__ void __launch_bounds__(128, 4) attn_hmma_kernel()
{
    extern __shared__ __align__(16) char dsm[];
    const uint32_t uQ = smem_u32(dsm);
    const uint32_t uK = uQ + 8192;
    const uint32_t uV = uK + 16384;

    const int tid  = threadIdx.x;
    const int wid  = tid >> 5;     // 0..3
    const int lane = tid & 31;
    const int h  = blockIdx.y;
    const int bb = blockIdx.z;
    const int wr0 = wid * 16;

    const __half* __restrict__ kp = g_kh + ((size_t)(bb * HH + h) * NN) * HDIM;
    const __half* __restrict__ vp = g_vh + ((size_t)(bb * HH + h) * NN) * HDIM;

    const float slope2 = exp2f(-0.5f * (float)(h + 1)) * SCALE_LOG2;
    const float Dcut = 34.f / slope2;

    float a0[8];
    #pragma unroll
    for (int nb = 0; nb < 8; nb++)
        a0[nb] = slope2 * (float)(nb * 8 + (lane & 3) * 2);

    #define LOAD_KV(t, buf) do { \
        const __half* ksrc = kp + (size_t)(t) * 64 * HDIM; \
        const __half* vsrc = vp + (size_t)(t) * 64 * HDIM; \
        _Pragma("unroll") \
        for (int i = 0; i < 4; i++) { \
            int idx = i * 128 + tid; \
            int r = idx >> 3, c = idx & 7; \
            uint32_t so = (buf) * 8192 + r * 128 + ((c ^ (r & 7)) * 16); \
            cp16(uK + so, ksrc + (size_t)r * HDIM + c * 8); \
            cp16(uV + so, vsrc + (size_t)r * HDIM + c * 8); \
        } } while (0)

    for (int phase = 0; phase < 2; phase++) {
        const int qt = (phase == 0) ? (31 - blockIdx.x) : blockIdx.x;
        const int q0 = qt * 64;
        const int nkt = qt + 1;
        const int r0 = q0 + wr0 + (lane >> 2);
        const int r1 = r0 + 8;

        // tile cutoff: keys farther than Dcut give p == 0 in fp16 anyway
        int kt_lo = 0;
        {
            float a = (float)(q0 - 63) - Dcut;
            if (a > 0.f) kt_lo = ((int)a + 63) >> 6;
        }
        const int count = nkt - kt_lo;

        const __half* __restrict__ qp =
            g_qh + ((size_t)(bb * HH + h) * NN + q0) * HDIM;

        // stage Q tile (64 x 64 fp16)
        #pragma unroll
        for (int i = 0; i < 4; i++) {
            int idx = i * 128 + tid;
            int r = idx >> 3, c = idx & 7;
            cp16(uQ + r * 128 + ((c ^ (r & 7)) * 16), qp + (size_t)r * HDIM + c * 8);
        }
        CP_COMMIT();
        LOAD_KV(nkt - 1, 0); CP_COMMIT();
        CP_WAIT(1);            // Q resident
        __syncthreads();

        uint32_t qf[4][4];
        #pragma unroll
        for (int ks = 0; ks < 4; ks++) {
            int row = wr0 + (lane & 15);
            int c = 2 * ks + (lane >> 4);
            LDSM4(qf[ks], uQ + row * 128 + ((c ^ (row & 7)) * 16));
        }

        float m0 = 0.f, m1 = 0.f;
        float l0 = 0.f, l1 = 0.f;
        float o[8][4];
        #pragma unroll
        for (int nb = 0; nb < 8; nb++)
            #pragma unroll
            for (int j = 0; j < 4; j++) o[nb][j] = 0.f;

        for (int it = 0; it < count; it++) {
            const int kt  = nkt - 1 - it;
            const int buf = it & 1;
            if (it + 1 < count) {
                LOAD_KV(nkt - 2 - it, (it + 1) & 1);
                CP_COMMIT();
                CP_WAIT(1);
            } else {
                CP_WAIT(0);
            }
            __syncthreads();

            const uint32_t bK = uK + buf * 8192;
            const uint32_t bV = uV + buf * 8192;

            float c[8][4];
            #pragma unroll
            for (int nb = 0; nb < 8; nb++)
                #pragma unroll
                for (int j = 0; j < 4; j++) c[nb][j] = 0.f;

            #pragma unroll
            for (int ks = 0; ks < 4; ks++) {
                #pragma unroll
                for (int np = 0; np < 4; np++) {
                    uint32_t bf[4];
                    int row = np * 16 + (lane & 7) + ((lane >> 4) << 3);
                    int cc = 2 * ks + ((lane >> 3) & 1);
                    LDSM4(bf, bK + row * 128 + ((cc ^ (row & 7)) * 16));
                    mma16816(c[2 * np],     qf[ks], bf[0], bf[1]);
                    mma16816(c[2 * np + 1], qf[ks], bf[2], bf[3]);
                }
            }

            uint32_t ph[4][4];
            const float kadd = slope2 * (float)(kt * 64);
            if (it == 0) {
                float mx0 = -1e30f, mx1 = -1e30f;
                #pragma unroll
                for (int nb = 0; nb < 8; nb++) {
                    int col = kt * 64 + nb * 8 + (lane & 3) * 2;
                    float t = a0[nb] + kadd;
                    c[nb][0] = (col     > r0) ? -1e30f : c[nb][0] + t;
                    c[nb][1] = (col + 1 > r0) ? -1e30f : c[nb][1] + t + slope2;
                    c[nb][2] = (col     > r1) ? -1e30f : c[nb][2] + t;
                    c[nb][3] = (col + 1 > r1) ? -1e30f : c[nb][3] + t + slope2;
                    mx0 = fmaxf(mx0, fmaxf(c[nb][0], c[nb][1]));
                    mx1 = fmaxf(mx1, fmaxf(c[nb][2], c[nb][3]));
                }
                mx0 = fmaxf(mx0, __shfl_xor_sync(0xffffffffu, mx0, 1));
                mx0 = fmaxf(mx0, __shfl_xor_sync(0xffffffffu, mx0, 2));
                mx1 = fmaxf(mx1, __shfl_xor_sync(0xffffffffu, mx1, 1));
                mx1 = fmaxf(mx1, __shfl_xor_sync(0xffffffffu, mx1, 2));
                m0 = mx0;
                m1 = mx1;
                #pragma unroll
                for (int nb = 0; nb < 8; nb++) {
                    uint32_t pa = pack_h2(c[nb][0] - m0, c[nb][1] - m0);
                    uint32_t pb = pack_h2(c[nb][2] - m1, c[nb][3] - m1);
                    ph[nb >> 1][(nb & 1) * 2]     = h2exp2(pa);
                    ph[nb >> 1][(nb & 1) * 2 + 1] = h2exp2(pb);
                }
            } else {
                const float km0 = kadd - m0;
                const float km1 = kadd - m1;
                #pragma unroll
                for (int nb = 0; nb < 8; nb++) {
                    float t0 = a0[nb] + km0;
                    float t1 = a0[nb] + km1;
                    uint32_t pa = pack_h2(c[nb][0] + t0, c[nb][1] + t0 + slope2);
                    uint32_t pb = pack_h2(c[nb][2] + t1, c[nb][3] + t1 + slope2);
                    ph[nb >> 1][(nb & 1) * 2]     = h2exp2(pa);
                    ph[nb >> 1][(nb & 1) * 2 + 1] = h2exp2(pb);
                }
            }

            // l accumulation on the fma pipe
            {
                uint32_t s0 = 0u, s1 = 0u;
                #pragma unroll
                for (int q = 0; q < 4; q++) {
                    s0 = hadd2u(s0, ph[q][0]);
                    s0 = hadd2u(s0, ph[q][2]);
                    s1 = hadd2u(s1, ph[q][1]);
                    s1 = hadd2u(s1, ph[q][3]);
                }
                l0 += h2sum(s0);
                l1 += h2sum(s1);
            }

            // O += P . V
            #pragma unroll
            for (int kpi = 0; kpi < 4; kpi++) {
                #pragma unroll
                for (int np = 0; np < 4; np++) {
                    uint32_t vf[4];
                    int row = kpi * 16 + ((lane >> 3) & 1) * 8 + (lane & 7);
                    int cc = 2 * np + (lane >> 4);
                    LDSM4T(vf, bV + row * 128 + ((cc ^ (row & 7)) * 16));
                    mma16816(o[2 * np],     ph[kpi], vf[0], vf[1]);
                    mma16816(o[2 * np + 1], ph[kpi], vf[2], vf[3]);
                }
            }
            __syncthreads();
        }

        l0 += __shfl_xor_sync(0xffffffffu, l0, 1);
        l0 += __shfl_xor_sync(0xffffffffu, l0, 2);
        l1 += __shfl_xor_sync(0xffffffffu, l1, 1);
        l1 += __shfl_xor_sync(0xffffffffu, l1, 2);
        const float inv0 = 1.f / l0;
        const float inv1 = 1.f / l1;
        #pragma unroll
        for (int nb = 0; nb < 8; nb++) {
            int colhd = nb * 8 + (lane & 3) * 2;
            size_t o0 = ((size_t)(bb * NN + r0)) * DD + h * HDIM + colhd;
            size_t o1 = ((size_t)(bb * NN + r1)) * DD + h * HDIM + colhd;
            *reinterpret_cast<__half2*>(g_ch + o0) =
                __floats2half2_rn(o[nb][0] * inv0, o[nb][1] * inv0);
            *reinterpret_cast<__half2*>(g_ch + o1) =
                __floats2half2_rn(o[nb][2] * inv1, o[nb][3] * inv1);
        }
        __syncthreads();
    }
    #undef LOAD_KV
}

// ---------------------------------------------------------------------------
extern "C" void kernel_launch(void* const* d_in, const int* in_sizes, int n_in,
                              void* d_out, int out_size)
{
    const float* x  = (const float*)d_in[0];
    const float* Wq = (const float*)d_in[1];
    const float* Wk = (const float*)d_in[2];
    const float* Wv = (const float*)d_in[3];
    const float* Wo = (const float*)d_in[4];
    const float* bo = (const float*)d_in[5];
    float* out = (float*)d_out;

    cudaFuncSetAttribute(gemm_hmma_kernel<true>,
                         cudaFuncAttributeMaxDynamicSharedMemorySize, GEMM_SMEM);
    cudaFuncSetAttribute(gemm_hmma_kernel<false>,
                         cudaFuncAttributeMaxDynamicSharedMemorySize, GEMM_SMEM);
    cudaFuncSetAttribute(attn_hmma_kernel,
                         cudaFuncAttributeMaxDynamicSharedMemorySize, ATTN_SMEM);

    __half* ch;
    cudaGetSymbolAddress((void**)&ch, g_ch);

    // QKV projections (A = x fp32, fused convert; B = W fp32, fused convert)
    gemm_hmma_kernel<true><<<dim3(8, 32, 3), 256, GEMM_SMEM>>>(
        x, nullptr, Wq, Wk, Wv, Wo, nullptr, nullptr, 0);

    // attention (balanced pairing, fixed-reference softmax, alibi cutoff)
    attn_hmma_kernel<<<dim3(16, HH, BB), 128, ATTN_SMEM>>>();

    // output projection (A = ctx fp16 via cp.async; B = Wo fp32 fused)
    gemm_hmma_kernel<false><<<dim3(8, 32, 1), 256, GEMM_SMEM>>>(
        nullptr, ch, Wq, Wk, Wv, Wo, bo, out, 3);
}

// round 16
// speedup vs baseline: 1.2986x; 1.2986x over previous
#include <cuda_runtime.h>
#include <cuda_fp16.h>
#include <math.h>
#include <stdint.h>

// Problem constants
#define BB 2
#define NN 2048
#define DD 1024
#define HH 16
#define HDIM 64
#define MM (BB*NN)   // 4096

// q pre-scale: (1/sqrt(64)) * log2(e)  -> softmax computed with exp2
#define SCALE_LOG2 0.18033688011112042f

// ---------------------------------------------------------------------------
// Device scratch
// ---------------------------------------------------------------------------
__device__ __half g_xh [MM*DD];
__device__ __half g_wh [4*DD*DD];   // weights fp16, ORIGINAL [k][n] layout
__device__ __half g_qh [BB*HH*NN*HDIM];  // pre-scaled by SCALE_LOG2
__device__ __half g_kh [BB*HH*NN*HDIM];
__device__ __half g_vh [BB*HH*NN*HDIM];
__device__ __half g_ch [MM*DD];     // ctx fp16

// ---------------------------------------------------------------------------
// PTX helpers (compute_103-safe: no 'a' features)
// ---------------------------------------------------------------------------
__device__ __forceinline__ uint32_t smem_u32(const void* p) {
    uint32_t a;
    asm("{ .reg .u64 t; cvta.to.shared.u64 t, %1; cvt.u32.u64 %0, t; }"
        : "=r"(a) : "l"(p));
    return a;
}
__device__ __forceinline__ void cp16(uint32_t dst, const void* src) {
    asm volatile("cp.async.cg.shared.global [%0], [%1], 16;" :: "r"(dst), "l"(src));
}
#define CP_COMMIT() asm volatile("cp.async.commit_group;")
#define CP_WAIT(n)  asm volatile("cp.async.wait_group %0;" :: "n"(n))

#define LDSM4(r, addr) \
    asm volatile("ldmatrix.sync.aligned.m8n8.x4.shared.b16 {%0,%1,%2,%3}, [%4];" \
        : "=r"((r)[0]), "=r"((r)[1]), "=r"((r)[2]), "=r"((r)[3]) : "r"(addr))
#define LDSM4T(r, addr) \
    asm volatile("ldmatrix.sync.aligned.m8n8.x4.trans.shared.b16 {%0,%1,%2,%3}, [%4];" \
        : "=r"((r)[0]), "=r"((r)[1]), "=r"((r)[2]), "=r"((r)[3]) : "r"(addr))

__device__ __forceinline__ void mma16816(float* d, const uint32_t* a,
                                         uint32_t b0, uint32_t b1) {
    asm volatile("mma.sync.aligned.m16n8k16.row.col.f32.f16.f16.f32 "
                 "{%0,%1,%2,%3}, {%4,%5,%6,%7}, {%8,%9}, {%0,%1,%2,%3};"
                 : "+f"(d[0]), "+f"(d[1]), "+f"(d[2]), "+f"(d[3])
                 : "r"(a[0]), "r"(a[1]), "r"(a[2]), "r"(a[3]), "r"(b0), "r"(b1));
}
__device__ __forceinline__ uint32_t pack_h2(float lo, float hi) {
    uint32_t r;
    asm("cvt.rn.f16x2.f32 %0, %1, %2;" : "=r"(r) : "f"(hi), "f"(lo));
    return r;
}
__device__ __forceinline__ uint32_t h2exp2(uint32_t x) {
    uint32_t y;
    asm("ex2.approx.f16x2 %0, %1;" : "=r"(y) : "r"(x));
    return y;
}
__device__ __forceinline__ uint32_t hadd2u(uint32_t a, uint32_t b) {
    uint32_t r;
    asm("add.f16x2 %0, %1, %2;" : "=r"(r) : "r"(a), "r"(b));
    return r;
}
__device__ __forceinline__ float h2sum(uint32_t v) {
    __half2 h = *reinterpret_cast<__half2*>(&v);
    return __half2float(__low2half(h)) + __half2float(__high2half(h));
}

// ---------------------------------------------------------------------------
// Prep: all fp32 -> fp16 converts in one launch.
// blocks [0,4096): x;  [4096, 8192): weights (1024 blocks per matrix).
// ---------------------------------------------------------------------------
__global__ void convert_all_kernel(const float* __restrict__ x,
                                   const float* __restrict__ Wq,
                                   const float* __restrict__ Wk,
                                   const float* __restrict__ Wv,
                                   const float* __restrict__ Wo)
{
    int bid = blockIdx.x;
    const float* src;
    __half* dst;
    int i;
    if (bid < 4096) {
        src = x; dst = g_xh;
        i = bid * 256 + threadIdx.x;
    } else {
        int t = bid - 4096;
        int mat = t >> 10;
        src = (mat == 0) ? Wq : (mat == 1) ? Wk : (mat == 2) ? Wv : Wo;
        dst = g_wh + (size_t)mat * DD * DD;
        i = (t & 1023) * 256 + threadIdx.x;
    }
    float4 v = reinterpret_cast<const float4*>(src)[i];
    reinterpret_cast<__half2*>(dst)[i * 2]     = __floats2half2_rn(v.x, v.y);
    reinterpret_cast<__half2*>(dst)[i * 2 + 1] = __floats2half2_rn(v.z, v.w);
}

// ---------------------------------------------------------------------------
// HMMA fp16 GEMM (round-13 configuration): C[128x128] tile, BK=64, 3-stage
// cp.async pipeline. B = W fp16 [k][n]; B fragments via ldmatrix.trans.
// mode 0/1/2 -> g_qh/g_kh/g_vh head-split fp16; mode 3 -> fp32 out + bias.
// smem: 3 x (A 16KB | B 16KB) = 96KB dynamic.
// ---------------------------------------------------------------------------
#define GEMM_SMEM (3 * 32768)

__global__ void __launch_bounds__(256, 2)
gemm_hmma_kernel(const __half* __restrict__ A,
                 const float* __restrict__ bias,
                 float* __restrict__ outp,
                 int mode_base)
{
    extern __shared__ __align__(16) char gsm[];
    const uint32_t uS = smem_u32(gsm);

    const int tid  = threadIdx.x;
    const int wid  = tid >> 5;
    const int lane = tid & 31;
    const int mode = mode_base + blockIdx.z;
    const int m0 = blockIdx.y * 128;
    const int n0 = blockIdx.x * 128;

    const __half* __restrict__ Ap = A + (size_t)m0 * DD;
    const __half* __restrict__ Bp = g_wh + (size_t)mode * DD * DD + n0;

    const int wm = (wid & 3) * 32;
    const int wn = (wid >> 2) * 64;

    float acc[2][8][4];
    #pragma unroll
    for (int i = 0; i < 2; i++)
        #pragma unroll
        for (int j = 0; j < 8; j++)
            #pragma unroll
            for (int q = 0; q < 4; q++) acc[i][j][q] = 0.f;

    #define LOAD_STAGE(k0v, buf) do { \
        _Pragma("unroll") \
        for (int i = 0; i < 4; i++) { \
            int idx = i * 256 + tid; \
            int ra = idx >> 3, ca = idx & 7; \
            cp16(uS + (buf) * 32768 + ra * 128 + ((ca ^ (ra & 7)) * 16), \
                 Ap + (size_t)ra * DD + (k0v) + ca * 8); \
            int rb = idx >> 4, qb = idx & 15; \
            int hb = qb >> 3, cb = qb & 7; \
            cp16(uS + (buf) * 32768 + 16384 + hb * 8192 + rb * 128 + ((cb ^ (rb & 7)) * 16), \
                 Bp + (size_t)((k0v) + rb) * DD + hb * 64 + cb * 8); \
        } } while (0)

    LOAD_STAGE(0, 0);  CP_COMMIT();
    LOAD_STAGE(64, 1); CP_COMMIT();

    const int NS = DD / 64;   // 16 stages
    for (int s = 0; s < NS; s++) {
        const int buf = s % 3;
        if (s + 2 < NS) {
            LOAD_STAGE((s + 2) * 64, (s + 2) % 3);
            CP_COMMIT();
            CP_WAIT(2);
        } else if (s + 1 < NS) {
            CP_WAIT(1);
        } else {
            CP_WAIT(0);
        }
        __syncthreads();

        const uint32_t bA  = uS + buf * 32768;
        const uint32_t bBh = bA + 16384 + (wid >> 2) * 8192;

        #pragma unroll
        for (int ks = 0; ks < 4; ks++) {
            uint32_t af[2][4];
            #pragma unroll
            for (int mt = 0; mt < 2; mt++) {
                int row = wm + mt * 16 + (lane & 15);
                int c = ks * 2 + (lane >> 4);
                LDSM4(af[mt], bA + row * 128 + ((c ^ (row & 7)) * 16));
            }
            #pragma unroll
            for (int np = 0; np < 4; np++) {
                uint32_t bf[4];
                int rowb = ks * 16 + ((lane >> 3) & 1) * 8 + (lane & 7);
                int ccb  = 2 * np + (lane >> 4);
                LDSM4T(bf, bBh + rowb * 128 + ((ccb ^ (rowb & 7)) * 16));
                #pragma unroll
                for (int mt = 0; mt < 2; mt++) {
                    mma16816(acc[mt][np * 2],     af[mt], bf[0], bf[1]);
                    mma16816(acc[mt][np * 2 + 1], af[mt], bf[2], bf[3]);
                }
            }
        }
        __syncthreads();
    }
    #undef LOAD_STAGE

    if (mode < 3) {
        const float scale = (mode == 0) ? SCALE_LOG2 : 1.0f;
        __half* __restrict__ dst = (mode == 0) ? g_qh : (mode == 1) ? g_kh : g_vh;
        #pragma unroll
        for (int mt = 0; mt < 2; mt++) {
            int r = m0 + wm + mt * 16 + (lane >> 2);
            int bbv = r >> 11, seq = r & 2047;
            #pragma unroll
            for (int nt = 0; nt < 8; nt++) {
                int col = n0 + wn + nt * 8 + (lane & 3) * 2;
                int hh = col >> 6, hd = col & 63;
                size_t o = ((size_t)(bbv * HH + hh) * NN + seq) * HDIM + hd;
                *reinterpret_cast<__half2*>(dst + o) =
                    __floats2half2_rn(acc[mt][nt][0] * scale, acc[mt][nt][1] * scale);
                *reinterpret_cast<__half2*>(dst + o + 8 * HDIM) =
                    __floats2half2_rn(acc[mt][nt][2] * scale, acc[mt][nt][3] * scale);
            }
        }
    } else {
        #pragma unroll
        for (int mt = 0; mt < 2; mt++) {
            int r = m0 + wm + mt * 16 + (lane >> 2);
            #pragma unroll
            for (int nt = 0; nt < 8; nt++) {
                int col = n0 + wn + nt * 8 + (lane & 3) * 2;
                float b0 = bias[col], b1 = bias[col + 1];
                *reinterpret_cast<float2*>(outp + (size_t)r * DD + col) =
                    make_float2(acc[mt][nt][0] + b0, acc[mt][nt][1] + b1);
                *reinterpret_cast<float2*>(outp + (size_t)(r + 8) * DD + col) =
                    make_float2(acc[mt][nt][2] + b0, acc[mt][nt][3] + b1);
            }
        }
    }
}

// ---------------------------------------------------------------------------
// HMMA flash attention (round-13 structure) + ALiBi tile cutoff:
// tiles with slope2*dist > 34 have p < 2^-24 (zero in the fp16 P path
// already) -> key-tile loop stops at kt_lo = ceil((q0-63-34/slope2)/64).
// Balanced pairing; reverse key order; fixed softmax reference m^ from the
// diagonal tile; l row-sum on the fma pipe.
// dynamic smem: Q 8KB | K 2x8KB | V 2x8KB = 40KB. grid (16,16,2), 128 thr.
// ---------------------------------------------------------------------------
#define ATTN_SMEM (40960)

__global__ void __launch_bounds__(128, 4) attn_hmma_kernel()
{
    extern __shared__ __align__(16) char dsm[];
    const uint32_t uQ = smem_u32(dsm);
    const uint32_t uK = uQ + 8192;
    const uint32_t uV = uK + 16384;

    const int tid  = threadIdx.x;
    const int wid  = tid >> 5;     // 0..3
    const int lane = tid & 31;
    const int h  = blockIdx.y;
    const int bb = blockIdx.z;
    const int wr0 = wid * 16;

    const __half* __restrict__ kp = g_kh + ((size_t)(bb * HH + h) * NN) * HDIM;
    const __half* __restrict__ vp = g_vh + ((size_t)(bb * HH + h) * NN) * HDIM;

    const float slope2 = exp2f(-0.5f * (float)(h + 1)) * SCALE_LOG2;
    const float Dcut = 34.f / slope2;

    float a0[8];
    #pragma unroll
    for (int nb = 0; nb < 8; nb++)
        a0[nb] = slope2 * (float)(nb * 8 + (lane & 3) * 2);

    #define LOAD_KV(t, buf) do { \
        const __half* ksrc = kp + (size_t)(t) * 64 * HDIM; \
        const __half* vsrc = vp + (size_t)(t) * 64 * HDIM; \
        _Pragma("unroll") \
        for (int i = 0; i < 4; i++) { \
            int idx = i * 128 + tid; \
            int r = idx >> 3, c = idx & 7; \
            uint32_t so = (buf) * 8192 + r * 128 + ((c ^ (r & 7)) * 16); \
            cp16(uK + so, ksrc + (size_t)r * HDIM + c * 8); \
            cp16(uV + so, vsrc + (size_t)r * HDIM + c * 8); \
        } } while (0)

    for (int phase = 0; phase < 2; phase++) {
        const int qt = (phase == 0) ? (31 - blockIdx.x) : blockIdx.x;
        const int q0 = qt * 64;
        const int nkt = qt + 1;
        const int r0 = q0 + wr0 + (lane >> 2);
        const int r1 = r0 + 8;

        // tile cutoff: keys farther than Dcut give p == 0 in fp16 anyway
        int kt_lo = 0;
        {
            float a = (float)(q0 - 63) - Dcut;
            if (a > 0.f) kt_lo = ((int)a + 63) >> 6;
        }
        const int count = nkt - kt_lo;

        const __half* __restrict__ qp =
            g_qh + ((size_t)(bb * HH + h) * NN + q0) * HDIM;

        // stage Q tile (64 x 64 fp16)
        #pragma unroll
        for (int i = 0; i < 4; i++) {
            int idx = i * 128 + tid;
            int r = idx >> 3, c = idx & 7;
            cp16(uQ + r * 128 + ((c ^ (r & 7)) * 16), qp + (size_t)r * HDIM + c * 8);
        }
        CP_COMMIT();
        LOAD_KV(nkt - 1, 0); CP_COMMIT();
        CP_WAIT(1);            // Q resident
        __syncthreads();

        uint32_t qf[4][4];
        #pragma unroll
        for (int ks = 0; ks < 4; ks++) {
            int row = wr0 + (lane & 15);
            int c = 2 * ks + (lane >> 4);
            LDSM4(qf[ks], uQ + row * 128 + ((c ^ (row & 7)) * 16));
        }

        float m0 = 0.f, m1 = 0.f;
        float l0 = 0.f, l1 = 0.f;
        float o[8][4];
        #pragma unroll
        for (int nb = 0; nb < 8; nb++)
            #pragma unroll
            for (int j = 0; j < 4; j++) o[nb][j] = 0.f;

        for (int it = 0; it < count; it++) {
            const int kt  = nkt - 1 - it;
            const int buf = it & 1;
            if (it + 1 < count) {
                LOAD_KV(nkt - 2 - it, (it + 1) & 1);
                CP_COMMIT();
                CP_WAIT(1);
            } else {
                CP_WAIT(0);
            }
            __syncthreads();

            const uint32_t bK = uK + buf * 8192;
            const uint32_t bV = uV + buf * 8192;

            float c[8][4];
            #pragma unroll
            for (int nb = 0; nb < 8; nb++)
                #pragma unroll
                for (int j = 0; j < 4; j++) c[nb][j] = 0.f;

            #pragma unroll
            for (int ks = 0; ks < 4; ks++) {
                #pragma unroll
                for (int np = 0; np < 4; np++) {
                    uint32_t bf[4];
                    int row = np * 16 + (lane & 7) + ((lane >> 4) << 3);
                    int cc = 2 * ks + ((lane >> 3) & 1);
                    LDSM4(bf, bK + row * 128 + ((cc ^ (row & 7)) * 16));
                    mma16816(c[2 * np],     qf[ks], bf[0], bf[1]);
                    mma16816(c[2 * np + 1], qf[ks], bf[2], bf[3]);
                }
            }

            uint32_t ph[4][4];
            const float kadd = slope2 * (float)(kt * 64);
            if (it == 0) {
                float mx0 = -1e30f, mx1 = -1e30f;
                #pragma unroll
                for (int nb = 0; nb < 8; nb++) {
                    int col = kt * 64 + nb * 8 + (lane & 3) * 2;
                    float t = a0[nb] + kadd;
                    c[nb][0] = (col     > r0) ? -1e30f : c[nb][0] + t;
                    c[nb][1] = (col + 1 > r0) ? -1e30f : c[nb][1] + t + slope2;
                    c[nb][2] = (col     > r1) ? -1e30f : c[nb][2] + t;
                    c[nb][3] = (col + 1 > r1) ? -1e30f : c[nb][3] + t + slope2;
                    mx0 = fmaxf(mx0, fmaxf(c[nb][0], c[nb][1]));
                    mx1 = fmaxf(mx1, fmaxf(c[nb][2], c[nb][3]));
                }
                mx0 = fmaxf(mx0, __shfl_xor_sync(0xffffffffu, mx0, 1));
                mx0 = fmaxf(mx0, __shfl_xor_sync(0xffffffffu, mx0, 2));
                mx1 = fmaxf(mx1, __shfl_xor_sync(0xffffffffu, mx1, 1));
                mx1 = fmaxf(mx1, __shfl_xor_sync(0xffffffffu, mx1, 2));
                m0 = mx0;
                m1 = mx1;
                #pragma unroll
                for (int nb = 0; nb < 8; nb++) {
                    uint32_t pa = pack_h2(c[nb][0] - m0, c[nb][1] - m0);
                    uint32_t pb = pack_h2(c[nb][2] - m1, c[nb][3] - m1);
                    ph[nb >> 1][(nb & 1) * 2]     = h2exp2(pa);
                    ph[nb >> 1][(nb & 1) * 2 + 1] = h2exp2(pb);
                }
            } else {
                const float km0 = kadd - m0;
                const float km1 = kadd - m1;
                #pragma unroll
                for (int nb = 0; nb < 8; nb++) {
                    float t0 = a0[nb] + km0;
                    float t1 = a0[nb] + km1;
                    uint32_t pa = pack_h2(c[nb][0] + t0, c[nb][1] + t0 + slope2);
                    uint32_t pb = pack_h2(c[nb][2] + t1, c[nb][3] + t1 + slope2);
                    ph[nb >> 1][(nb & 1) * 2]     = h2exp2(pa);
                    ph[nb >> 1][(nb & 1) * 2 + 1] = h2exp2(pb);
                }
            }

            // l accumulation on the fma pipe
            {
                uint32_t s0 = 0u, s1 = 0u;
                #pragma unroll
                for (int q = 0; q < 4; q++) {
                    s0 = hadd2u(s0, ph[q][0]);
                    s0 = hadd2u(s0, ph[q][2]);
                    s1 = hadd2u(s1, ph[q][1]);
                    s1 = hadd2u(s1, ph[q][3]);
                }
                l0 += h2sum(s0);
                l1 += h2sum(s1);
            }

            // O += P . V
            #pragma unroll
            for (int kpi = 0; kpi < 4; kpi++) {
                #pragma unroll
                for (int np = 0; np < 4; np++) {
                    uint32_t vf[4];
                    int row = kpi * 16 + ((lane >> 3) & 1) * 8 + (lane & 7);
                    int cc = 2 * np + (lane >> 4);
                    LDSM4T(vf, bV + row * 128 + ((cc ^ (row & 7)) * 16));
                    mma16816(o[2 * np],     ph[kpi], vf[0], vf[1]);
                    mma16816(o[2 * np + 1], ph[kpi], vf[2], vf[3]);
                }
            }
            __syncthreads();
        }

        l0 += __shfl_xor_sync(0xffffffffu, l0, 1);
        l0 += __shfl_xor_sync(0xffffffffu, l0, 2);
        l1 += __shfl_xor_sync(0xffffffffu, l1, 1);
        l1 += __shfl_xor_sync(0xffffffffu, l1, 2);
        const float inv0 = 1.f / l0;
        const float inv1 = 1.f / l1;
        #pragma unroll
        for (int nb = 0; nb < 8; nb++) {
            int colhd = nb * 8 + (lane & 3) * 2;
            size_t o0 = ((size_t)(bb * NN + r0)) * DD + h * HDIM + colhd;
            size_t o1 = ((size_t)(bb * NN + r1)) * DD + h * HDIM + colhd;
            *reinterpret_cast<__half2*>(g_ch + o0) =
                __floats2half2_rn(o[nb][0] * inv0, o[nb][1] * inv0);
            *reinterpret_cast<__half2*>(g_ch + o1) =
                __floats2half2_rn(o[nb][2] * inv1, o[nb][3] * inv1);
        }
        __syncthreads();
    }
    #undef LOAD_KV
}

// ---------------------------------------------------------------------------
extern "C" void kernel_launch(void* const* d_in, const int* in_sizes, int n_in,
                              void* d_out, int out_size)
{
    const float* x  = (const float*)d_in[0];
    const float* Wq = (const float*)d_in[1];
    const float* Wk = (const float*)d_in[2];
    const float* Wv = (const float*)d_in[3];
    const float* Wo = (const float*)d_in[4];
    const float* bo = (const float*)d_in[5];
    float* out = (float*)d_out;

    cudaFuncSetAttribute(gemm_hmma_kernel,
                         cudaFuncAttributeMaxDynamicSharedMemorySize, GEMM_SMEM);
    cudaFuncSetAttribute(attn_hmma_kernel,
                         cudaFuncAttributeMaxDynamicSharedMemorySize, ATTN_SMEM);

    __half *xh, *ch;
    cudaGetSymbolAddress((void**)&xh, g_xh);
    cudaGetSymbolAddress((void**)&ch, g_ch);

    convert_all_kernel<<<8192, 256>>>(x, Wq, Wk, Wv, Wo);

    // QKV projections
    gemm_hmma_kernel<<<dim3(8, 32, 3), 256, GEMM_SMEM>>>(xh, nullptr, nullptr, 0);

    // attention (balanced pairing, fixed-reference softmax, alibi cutoff)
    attn_hmma_kernel<<<dim3(16, HH, BB), 128, ATTN_SMEM>>>();

    // output projection
    gemm_hmma_kernel<<<dim3(8, 32, 1), 256, GEMM_SMEM>>>(ch, bo, out, 3);
}

// round 17
// speedup vs baseline: 1.3576x; 1.0454x over previous
#include <cuda_runtime.h>
#include <cuda_fp16.h>
#include <math.h>
#include <stdint.h>

// Problem constants
#define BB 2
#define NN 2048
#define DD 1024
#define HH 16
#define HDIM 64
#define MM (BB*NN)   // 4096

// q pre-scale: (1/sqrt(64)) * log2(e)  -> softmax computed with exp2
#define SCALE_LOG2 0.18033688011112042f

#define NWORK 1024          // 2 * 16 * 32 work items
#define ATTN_GRID 592       // 148 SMs x 4 CTAs

// ---------------------------------------------------------------------------
// Device scratch
// ---------------------------------------------------------------------------
__device__ __half g_xh [MM*DD];
__device__ __half g_wh [4*DD*DD];   // weights fp16, ORIGINAL [k][n] layout
__device__ __half g_qh [BB*HH*NN*HDIM];  // pre-scaled by SCALE_LOG2
__device__ __half g_kh [BB*HH*NN*HDIM];
__device__ __half g_vh [BB*HH*NN*HDIM];
__device__ __half g_ch [MM*DD];     // ctx fp16
__device__ uint32_t g_sched[NWORK]; // work items sorted by cost desc
__device__ int g_ctr;               // work-queue counter

// ---------------------------------------------------------------------------
// PTX helpers (compute_103-safe: no 'a' features)
// ---------------------------------------------------------------------------
__device__ __forceinline__ uint32_t smem_u32(const void* p) {
    uint32_t a;
    asm("{ .reg .u64 t; cvta.to.shared.u64 t, %1; cvt.u32.u64 %0, t; }"
        : "=r"(a) : "l"(p));
    return a;
}
__device__ __forceinline__ void cp16(uint32_t dst, const void* src) {
    asm volatile("cp.async.cg.shared.global [%0], [%1], 16;" :: "r"(dst), "l"(src));
}
#define CP_COMMIT() asm volatile("cp.async.commit_group;")
#define CP_WAIT(n)  asm volatile("cp.async.wait_group %0;" :: "n"(n))

#define LDSM4(r, addr) \
    asm volatile("ldmatrix.sync.aligned.m8n8.x4.shared.b16 {%0,%1,%2,%3}, [%4];" \
        : "=r"((r)[0]), "=r"((r)[1]), "=r"((r)[2]), "=r"((r)[3]) : "r"(addr))
#define LDSM4T(r, addr) \
    asm volatile("ldmatrix.sync.aligned.m8n8.x4.trans.shared.b16 {%0,%1,%2,%3}, [%4];" \
        : "=r"((r)[0]), "=r"((r)[1]), "=r"((r)[2]), "=r"((r)[3]) : "r"(addr))

__device__ __forceinline__ void mma16816(float* d, const uint32_t* a,
                                         uint32_t b0, uint32_t b1) {
    asm volatile("mma.sync.aligned.m16n8k16.row.col.f32.f16.f16.f32 "
                 "{%0,%1,%2,%3}, {%4,%5,%6,%7}, {%8,%9}, {%0,%1,%2,%3};"
                 : "+f"(d[0]), "+f"(d[1]), "+f"(d[2]), "+f"(d[3])
                 : "r"(a[0]), "r"(a[1]), "r"(a[2]), "r"(a[3]), "r"(b0), "r"(b1));
}
__device__ __forceinline__ uint32_t pack_h2(float lo, float hi) {
    uint32_t r;
    asm("cvt.rn.f16x2.f32 %0, %1, %2;" : "=r"(r) : "f"(hi), "f"(lo));
    return r;
}
__device__ __forceinline__ uint32_t h2exp2(uint32_t x) {
    uint32_t y;
    asm("ex2.approx.f16x2 %0, %1;" : "=r"(y) : "r"(x));
    return y;
}
__device__ __forceinline__ uint32_t hadd2u(uint32_t a, uint32_t b) {
    uint32_t r;
    asm("add.f16x2 %0, %1, %2;" : "=r"(r) : "r"(a), "r"(b));
    return r;
}
__device__ __forceinline__ float h2sum(uint32_t v) {
    __half2 h = *reinterpret_cast<__half2*>(&v);
    return __half2float(__low2half(h)) + __half2float(__high2half(h));
}

// shared cost model: number of key tiles actually processed for (h, qt)
__device__ __forceinline__ int work_count(int h, int qt) {
    float slope2 = exp2f(-0.5f * (float)(h + 1)) * SCALE_LOG2;
    float Dcut = 34.f / slope2;
    int kt_lo = 0;
    float a = (float)(qt * 64 - 63) - Dcut;
    if (a > 0.f) kt_lo = ((int)a + 63) >> 6;
    return (qt + 1) - kt_lo;
}

// ---------------------------------------------------------------------------
// Prep: fp32 -> fp16 converts + build the sorted work schedule + reset counter.
// blocks [0,4096): x;  [4096, 8192): weights;  block 8192: schedule.
// ---------------------------------------------------------------------------
__global__ void prep_kernel(const float* __restrict__ x,
                            const float* __restrict__ Wq,
                            const float* __restrict__ Wk,
                            const float* __restrict__ Wv,
                            const float* __restrict__ Wo)
{
    int bid = blockIdx.x;
    if (bid == 8192) {
        // build schedule: counting sort of 512 (h,qt) items by cost desc; x2 bb
        __shared__ int hist[36];
        __shared__ int base[36];
        int t = threadIdx.x;           // 0..511 (h*32+qt)
        if (t < 36) hist[t] = 0;
        __syncthreads();
        int h = t >> 5, qt = t & 31;
        int cost = work_count(h, qt);  // 1..33
        atomicAdd(&hist[cost], 2);     // two bb copies
        __syncthreads();
        if (t == 0) {
            g_ctr = 0;
            int acc = 0;
            for (int cst = 33; cst >= 1; cst--) {   // descending cost
                base[cst] = acc;
                acc += hist[cst];
            }
        }
        __syncthreads();
        int pos = atomicAdd(&base[cost], 2);
        g_sched[pos]     = (0u << 9) | (h << 5) | qt;
        g_sched[pos + 1] = (1u << 9) | (h << 5) | qt;
        return;
    }
    const float* src;
    __half* dst;
    int i;
    if (bid < 4096) {
        src = x; dst = g_xh;
        i = bid * 256 + threadIdx.x;
    } else {
        int t2 = bid - 4096;
        int mat = t2 >> 10;
        src = (mat == 0) ? Wq : (mat == 1) ? Wk : (mat == 2) ? Wv : Wo;
        dst = g_wh + (size_t)mat * DD * DD;
        i = (t2 & 1023) * 256 + threadIdx.x;
    }
    float4 v = reinterpret_cast<const float4*>(src)[i];
    reinterpret_cast<__half2*>(dst)[i * 2]     = __floats2half2_rn(v.x, v.y);
    reinterpret_cast<__half2*>(dst)[i * 2 + 1] = __floats2half2_rn(v.z, v.w);
}

// ---------------------------------------------------------------------------
// HMMA fp16 GEMM (round-13 configuration): C[128x128] tile, BK=64, 3-stage
// cp.async pipeline. B = W fp16 [k][n]; B fragments via ldmatrix.trans.
// mode 0/1/2 -> g_qh/g_kh/g_vh head-split fp16; mode 3 -> fp32 out + bias.
// smem: 3 x (A 16KB | B 16KB) = 96KB dynamic.
// ---------------------------------------------------------------------------
#define GEMM_SMEM (3 * 32768)

__global__ void __launch_bounds__(256, 2)
gemm_hmma_kernel(const __half* __restrict__ A,
                 const float* __restrict__ bias,
                 float* __restrict__ outp,
                 int mode_base)
{
    extern __shared__ __align__(16) char gsm[];
    const uint32_t uS = smem_u32(gsm);

    const int tid  = threadIdx.x;
    const int wid  = tid >> 5;
    const int lane = tid & 31;
    const int mode = mode_base + blockIdx.z;
    const int m0 = blockIdx.y * 128;
    const int n0 = blockIdx.x * 128;

    const __half* __restrict__ Ap = A + (size_t)m0 * DD;
    const __half* __restrict__ Bp = g_wh + (size_t)mode * DD * DD + n0;

    const int wm = (wid & 3) * 32;
    const int wn = (wid >> 2) * 64;

    float acc[2][8][4];
    #pragma unroll
    for (int i = 0; i < 2; i++)
        #pragma unroll
        for (int j = 0; j < 8; j++)
            #pragma unroll
            for (int q = 0; q < 4; q++) acc[i][j][q] = 0.f;

    #define LOAD_STAGE(k0v, buf) do { \
        _Pragma("unroll") \
        for (int i = 0; i < 4; i++) { \
            int idx = i * 256 + tid; \
            int ra = idx >> 3, ca = idx & 7; \
            cp16(uS + (buf) * 32768 + ra * 128 + ((ca ^ (ra & 7)) * 16), \
                 Ap + (size_t)ra * DD + (k0v) + ca * 8); \
            int rb = idx >> 4, qb = idx & 15; \
            int hb = qb >> 3, cb = qb & 7; \
            cp16(uS + (buf) * 32768 + 16384 + hb * 8192 + rb * 128 + ((cb ^ (rb & 7)) * 16), \
                 Bp + (size_t)((k0v) + rb) * DD + hb * 64 + cb * 8); \
        } } while (0)

    LOAD_STAGE(0, 0);  CP_COMMIT();
    LOAD_STAGE(64, 1); CP_COMMIT();

    const int NS = DD / 64;   // 16 stages
    for (int s = 0; s < NS; s++) {
        const int buf = s % 3;
        if (s + 2 < NS) {
            LOAD_STAGE((s + 2) * 64, (s + 2) % 3);
            CP_COMMIT();
            CP_WAIT(2);
        } else if (s + 1 < NS) {
            CP_WAIT(1);
        } else {
            CP_WAIT(0);
        }
        __syncthreads();

        const uint32_t bA  = uS + buf * 32768;
        const uint32_t bBh = bA + 16384 + (wid >> 2) * 8192;

        #pragma unroll
        for (int ks = 0; ks < 4; ks++) {
            uint32_t af[2][4];
            #pragma unroll
            for (int mt = 0; mt < 2; mt++) {
                int row = wm + mt * 16 + (lane & 15);
                int c = ks * 2 + (lane >> 4);
                LDSM4(af[mt], bA + row * 128 + ((c ^ (row & 7)) * 16));
            }
            #pragma unroll
            for (int np = 0; np < 4; np++) {
                uint32_t bf[4];
                int rowb = ks * 16 + ((lane >> 3) & 1) * 8 + (lane & 7);
                int ccb  = 2 * np + (lane >> 4);
                LDSM4T(bf, bBh + rowb * 128 + ((ccb ^ (rowb & 7)) * 16));
                #pragma unroll
                for (int mt = 0; mt < 2; mt++) {
                    mma16816(acc[mt][np * 2],     af[mt], bf[0], bf[1]);
                    mma16816(acc[mt][np * 2 + 1], af[mt], bf[2], bf[3]);
                }
            }
        }
        __syncthreads();
    }
    #undef LOAD_STAGE

    if (mode < 3) {
        const float scale = (mode == 0) ? SCALE_LOG2 : 1.0f;
        __half* __restrict__ dst = (mode == 0) ? g_qh : (mode == 1) ? g_kh : g_vh;
        #pragma unroll
        for (int mt = 0; mt < 2; mt++) {
            int r = m0 + wm + mt * 16 + (lane >> 2);
            int bbv = r >> 11, seq = r & 2047;
            #pragma unroll
            for (int nt = 0; nt < 8; nt++) {
                int col = n0 + wn + nt * 8 + (lane & 3) * 2;
                int hh = col >> 6, hd = col & 63;
                size_t o = ((size_t)(bbv * HH + hh) * NN + seq) * HDIM + hd;
                *reinterpret_cast<__half2*>(dst + o) =
                    __floats2half2_rn(acc[mt][nt][0] * scale, acc[mt][nt][1] * scale);
                *reinterpret_cast<__half2*>(dst + o + 8 * HDIM) =
                    __floats2half2_rn(acc[mt][nt][2] * scale, acc[mt][nt][3] * scale);
            }
        }
    } else {
        #pragma unroll
        for (int mt = 0; mt < 2; mt++) {
            int r = m0 + wm + mt * 16 + (lane >> 2);
            #pragma unroll
            for (int nt = 0; nt < 8; nt++) {
                int col = n0 + wn + nt * 8 + (lane & 3) * 2;
                float b0 = bias[col], b1 = bias[col + 1];
                *reinterpret_cast<float2*>(outp + (size_t)r * DD + col) =
                    make_float2(acc[mt][nt][0] + b0, acc[mt][nt][1] + b1);
                *reinterpret_cast<float2*>(outp + (size_t)(r + 8) * DD + col) =
                    make_float2(acc[mt][nt][2] + b0, acc[mt][nt][3] + b1);
            }
        }
    }
}

// ---------------------------------------------------------------------------
// Persistent HMMA flash attention with cost-sorted work queue.
// 592 CTAs pull (bb,h,qt) items via atomicAdd (longest-processing-time-first
// -> balanced wave; the alibi cutoff savings now shorten the critical path).
// Inner loop identical to round-16: reverse key order, fixed softmax ref m^,
// fp16 exp2 softmax, l row-sum on the fma pipe, alibi tile cutoff.
// dynamic smem: Q 8KB | K 2x8KB | V 2x8KB = 40KB. 128 threads.
// ---------------------------------------------------------------------------
#define ATTN_SMEM (40960)

__global__ void __launch_bounds__(128, 4) attn_hmma_kernel()
{
    extern __shared__ __align__(16) char dsm[];
    const uint32_t uQ = smem_u32(dsm);
    const uint32_t uK = uQ + 8192;
    const uint32_t uV = uK + 16384;
    __shared__ int s_idx;

    const int tid  = threadIdx.x;
    const int wid  = tid >> 5;     // 0..3
    const int lane = tid & 31;
    const int wr0 = wid * 16;

    for (;;) {
        if (tid == 0) s_idx = atomicAdd(&g_ctr, 1);
        __syncthreads();
        const int idx = s_idx;
        if (idx >= NWORK) break;
        const uint32_t w = g_sched[idx];
        const int bb = w >> 9;
        const int h  = (w >> 5) & 15;
        const int qt = w & 31;

        const __half* __restrict__ kp = g_kh + ((size_t)(bb * HH + h) * NN) * HDIM;
        const __half* __restrict__ vp = g_vh + ((size_t)(bb * HH + h) * NN) * HDIM;

        const float slope2 = exp2f(-0.5f * (float)(h + 1)) * SCALE_LOG2;
        const float Dcut = 34.f / slope2;

        float a0[8];
        #pragma unroll
        for (int nb = 0; nb < 8; nb++)
            a0[nb] = slope2 * (float)(nb * 8 + (lane & 3) * 2);

        #define LOAD_KV(t, buf) do { \
            const __half* ksrc = kp + (size_t)(t) * 64 * HDIM; \
            const __half* vsrc = vp + (size_t)(t) * 64 * HDIM; \
            _Pragma("unroll") \
            for (int i = 0; i < 4; i++) { \
                int idx2 = i * 128 + tid; \
                int r = idx2 >> 3, c = idx2 & 7; \
                uint32_t so = (buf) * 8192 + r * 128 + ((c ^ (r & 7)) * 16); \
                cp16(uK + so, ksrc + (size_t)r * HDIM + c * 8); \
                cp16(uV + so, vsrc + (size_t)r * HDIM + c * 8); \
            } } while (0)

        const int q0 = qt * 64;
        const int nkt = qt + 1;
        const int r0 = q0 + wr0 + (lane >> 2);
        const int r1 = r0 + 8;

        int kt_lo = 0;
        {
            float a = (float)(q0 - 63) - Dcut;
            if (a > 0.f) kt_lo = ((int)a + 63) >> 6;
        }
        const int count = nkt - kt_lo;

        const __half* __restrict__ qp =
            g_qh + ((size_t)(bb * HH + h) * NN + q0) * HDIM;

        // stage Q tile (64 x 64 fp16)
        #pragma unroll
        for (int i = 0; i < 4; i++) {
            int idx2 = i * 128 + tid;
            int r = idx2 >> 3, c = idx2 & 7;
            cp16(uQ + r * 128 + ((c ^ (r & 7)) * 16), qp + (size_t)r * HDIM + c * 8);
        }
        CP_COMMIT();
        LOAD_KV(nkt - 1, 0); CP_COMMIT();
        CP_WAIT(1);            // Q resident
        __syncthreads();

        uint32_t qf[4][4];
        #pragma unroll
        for (int ks = 0; ks < 4; ks++) {
            int row = wr0 + (lane & 15);
            int c = 2 * ks + (lane >> 4);
            LDSM4(qf[ks], uQ + row * 128 + ((c ^ (row & 7)) * 16));
        }

        float m0 = 0.f, m1 = 0.f;
        float l0 = 0.f, l1 = 0.f;
        float o[8][4];
        #pragma unroll
        for (int nb = 0; nb < 8; nb++)
            #pragma unroll
            for (int j = 0; j < 4; j++) o[nb][j] = 0.f;

        for (int it = 0; it < count; it++) {
            const int kt  = nkt - 1 - it;
            const int buf = it & 1;
            if (it + 1 < count) {
                LOAD_KV(nkt - 2 - it, (it + 1) & 1);
                CP_COMMIT();
                CP_WAIT(1);
            } else {
                CP_WAIT(0);
            }
            __syncthreads();

            const uint32_t bK = uK + buf * 8192;
            const uint32_t bV = uV + buf * 8192;

            float c[8][4];
            #pragma unroll
            for (int nb = 0; nb < 8; nb++)
                #pragma unroll
                for (int j = 0; j < 4; j++) c[nb][j] = 0.f;

            #pragma unroll
            for (int ks = 0; ks < 4; ks++) {
                #pragma unroll
                for (int np = 0; np < 4; np++) {
                    uint32_t bf[4];
                    int row = np * 16 + (lane & 7) + ((lane >> 4) << 3);
                    int cc = 2 * ks + ((lane >> 3) & 1);
                    LDSM4(bf, bK + row * 128 + ((cc ^ (row & 7)) * 16));
                    mma16816(c[2 * np],     qf[ks], bf[0], bf[1]);
                    mma16816(c[2 * np + 1], qf[ks], bf[2], bf[3]);
                }
            }

            uint32_t ph[4][4];
            const float kadd = slope2 * (float)(kt * 64);
            if (it == 0) {
                float mx0 = -1e30f, mx1 = -1e30f;
                #pragma unroll
                for (int nb = 0; nb < 8; nb++) {
                    int col = kt * 64 + nb * 8 + (lane & 3) * 2;
                    float t = a0[nb] + kadd;
                    c[nb][0] = (col     > r0) ? -1e30f : c[nb][0] + t;
                    c[nb][1] = (col + 1 > r0) ? -1e30f : c[nb][1] + t + slope2;
                    c[nb][2] = (col     > r1) ? -1e30f : c[nb][2] + t;
                    c[nb][3] = (col + 1 > r1) ? -1e30f : c[nb][3] + t + slope2;
                    mx0 = fmaxf(mx0, fmaxf(c[nb][0], c[nb][1]));
                    mx1 = fmaxf(mx1, fmaxf(c[nb][2], c[nb][3]));
                }
                mx0 = fmaxf(mx0, __shfl_xor_sync(0xffffffffu, mx0, 1));
                mx0 = fmaxf(mx0, __shfl_xor_sync(0xffffffffu, mx0, 2));
                mx1 = fmaxf(mx1, __shfl_xor_sync(0xffffffffu, mx1, 1));
                mx1 = fmaxf(mx1, __shfl_xor_sync(0xffffffffu, mx1, 2));
                m0 = mx0;
                m1 = mx1;
                #pragma unroll
                for (int nb = 0; nb < 8; nb++) {
                    uint32_t pa = pack_h2(c[nb][0] - m0, c[nb][1] - m0);
                    uint32_t pb = pack_h2(c[nb][2] - m1, c[nb][3] - m1);
                    ph[nb >> 1][(nb & 1) * 2]     = h2exp2(pa);
                    ph[nb >> 1][(nb & 1) * 2 + 1] = h2exp2(pb);
                }
            } else {
                const float km0 = kadd - m0;
                const float km1 = kadd - m1;
                #pragma unroll
                for (int nb = 0; nb < 8; nb++) {
                    float t0 = a0[nb] + km0;
                    float t1 = a0[nb] + km1;
                    uint32_t pa = pack_h2(c[nb][0] + t0, c[nb][1] + t0 + slope2);
                    uint32_t pb = pack_h2(c[nb][2] + t1, c[nb][3] + t1 + slope2);
                    ph[nb >> 1][(nb & 1) * 2]     = h2exp2(pa);
                    ph[nb >> 1][(nb & 1) * 2 + 1] = h2exp2(pb);
                }
            }

            // l accumulation on the fma pipe
            {
                uint32_t s0 = 0u, s1 = 0u;
                #pragma unroll
                for (int q = 0; q < 4; q++) {
                    s0 = hadd2u(s0, ph[q][0]);
                    s0 = hadd2u(s0, ph[q][2]);
                    s1 = hadd2u(s1, ph[q][1]);
                    s1 = hadd2u(s1, ph[q][3]);
                }
                l0 += h2sum(s0);
                l1 += h2sum(s1);
            }

            // O += P . V
            #pragma unroll
            for (int kpi = 0; kpi < 4; kpi++) {
                #pragma unroll
                for (int np = 0; np < 4; np++) {
                    uint32_t vf[4];
                    int row = kpi * 16 + ((lane >> 3) & 1) * 8 + (lane & 7);
                    int cc = 2 * np + (lane >> 4);
                    LDSM4T(vf, bV + row * 128 + ((cc ^ (row & 7)) * 16));
                    mma16816(o[2 * np],     ph[kpi], vf[0], vf[1]);
                    mma16816(o[2 * np + 1], ph[kpi], vf[2], vf[3]);
                }
            }
            __syncthreads();
        }
        #undef LOAD_KV

        l0 += __shfl_xor_sync(0xffffffffu, l0, 1);
        l0 += __shfl_xor_sync(0xffffffffu, l0, 2);
        l1 += __shfl_xor_sync(0xffffffffu, l1, 1);
        l1 += __shfl_xor_sync(0xffffffffu, l1, 2);
        const float inv0 = 1.f / l0;
        const float inv1 = 1.f / l1;
        #pragma unroll
        for (int nb = 0; nb < 8; nb++) {
            int colhd = nb * 8 + (lane & 3) * 2;
            size_t o0 = ((size_t)(bb * NN + r0)) * DD + h * HDIM + colhd;
            size_t o1 = ((size_t)(bb * NN + r1)) * DD + h * HDIM + colhd;
            *reinterpret_cast<__half2*>(g_ch + o0) =
                __floats2half2_rn(o[nb][0] * inv0, o[nb][1] * inv0);
            *reinterpret_cast<__half2*>(g_ch + o1) =
                __floats2half2_rn(o[nb][2] * inv1, o[nb][3] * inv1);
        }
        __syncthreads();   // smem + s_idx safe for next item
    }
}

// ---------------------------------------------------------------------------
extern "C" void kernel_launch(void* const* d_in, const int* in_sizes, int n_in,
                              void* d_out, int out_size)
{
    const float* x  = (const float*)d_in[0];
    const float* Wq = (const float*)d_in[1];
    const float* Wk = (const float*)d_in[2];
    const float* Wv = (const float*)d_in[3];
    const float* Wo = (const float*)d_in[4];
    const float* bo = (const float*)d_in[5];
    float* out = (float*)d_out;

    cudaFuncSetAttribute(gemm_hmma_kernel,
                         cudaFuncAttributeMaxDynamicSharedMemorySize, GEMM_SMEM);
    cudaFuncSetAttribute(attn_hmma_kernel,
                         cudaFuncAttributeMaxDynamicSharedMemorySize, ATTN_SMEM);

    __half *xh, *ch;
    cudaGetSymbolAddress((void**)&xh, g_xh);
    cudaGetSymbolAddress((void**)&ch, g_ch);

    // converts + schedule build + counter reset
    prep_kernel<<<8193, 512>>>(x, Wq, Wk, Wv, Wo);

    // QKV projections
    gemm_hmma_kernel<<<dim3(8, 32, 3), 256, GEMM_SMEM>>>(xh, nullptr, nullptr, 0);

    // attention: persistent CTAs + LPT work queue + alibi cutoff
    attn_hmma_kernel<<<ATTN_GRID, 128, ATTN_SMEM>>>();

    // output projection
    gemm_hmma_kernel<<<dim3(8, 32, 1), 256, GEMM_SMEM>>>(ch, bo, out, 3);
}